// round 6
// baseline (speedup 1.0000x reference)
#include <cuda_runtime.h>
#include <cstdint>

typedef unsigned long long u64;

#define NB   8192
#define SS   64
#define NXX  4
#define NSF  5
#define HH   32
#define WPB  4          // warps per block
#define SPW  2          // batch streams per warp
#define BPB  (WPB*SPW)  // 8 batch elements per block
#define CH   4          // layer-2 time chunk
#define FULLMASK 0xffffffffu

// ---------- packed f32x2 helpers ----------
static __device__ __forceinline__ u64 ffma2(u64 a, u64 b, u64 c) {
    u64 d; asm("fma.rn.f32x2 %0, %1, %2, %3;" : "=l"(d) : "l"(a), "l"(b), "l"(c)); return d;
}
static __device__ __forceinline__ u64 pk2(float lo, float hi) {
    u64 r; asm("mov.b64 %0, {%1, %2};" : "=l"(r) : "f"(lo), "f"(hi)); return r;
}
static __device__ __forceinline__ u64 pklo(float lo) {
    u64 r; asm("mov.b64 %0, {%1, %2};" : "=l"(r) : "f"(lo), "f"(0.0f)); return r;
}
static __device__ __forceinline__ void up2(u64 v, float& lo, float& hi) {
    asm("mov.b64 {%0, %1}, %2;" : "=f"(lo), "=f"(hi) : "l"(v));
}
static __device__ __forceinline__ float hsum2(u64 v) {
    float x, y; up2(v, x, y); return x + y;
}

// ---------- fast activations (MUFU.TANH) ----------
static __device__ __forceinline__ float tanh_ap(float x) {
    float r; asm("tanh.approx.f32 %0, %1;" : "=f"(r) : "f"(x)); return r;
}
static __device__ __forceinline__ float sigm(float x) {
    return fmaf(tanh_ap(0.5f * x), 0.5f, 0.5f);
}

// ---- shared memory (bytes) ----
// w2t : ulonglong2[2][8][128]  layer-2 weights                       32768
// sy  : float[8][64*32]        layer-1 outputs                       65536
// sxg : u64[8][CH][2][32]      phase-A gate results (lane-private)   16384
// hb  : float[8][2][32]        h broadcast double buffers             2048
#define OFF_W2T  0
#define OFF_SY   32768
#define OFF_SXG  (32768 + 65536)
#define OFF_HB   (OFF_SXG + 16384)
#define SMEM_BYTES (OFF_HB + 2048)

__global__ void __launch_bounds__(WPB * 32, 2)
lstm_fused6(const float* __restrict__ x_main,
            const float* __restrict__ x_sfc,
            const float* __restrict__ w_sfc1, const float* __restrict__ b_sfc1,
            const float* __restrict__ w_sfc2, const float* __restrict__ b_sfc2,
            const float* __restrict__ w_ih1,  const float* __restrict__ w_hh1,
            const float* __restrict__ b_ih1,  const float* __restrict__ b_hh1,
            const float* __restrict__ w_ih2,  const float* __restrict__ w_hh2,
            const float* __restrict__ b_ih2,  const float* __restrict__ b_hh2,
            const float* __restrict__ w_out,  const float* __restrict__ b_out,
            float* __restrict__ out)
{
    extern __shared__ char smem[];
    ulonglong2* w2t = (ulonglong2*)(smem + OFF_W2T);   // [(m*8+qq)*128 + row]
    float* sy  = (float*)(smem + OFF_SY);
    u64*   sxg = (u64*)(smem + OFF_SXG);
    float* hb  = (float*)(smem + OFF_HB);

    const int tid  = threadIdx.x;
    const int wid  = tid >> 5;
    const int lane = tid & 31;
    const int bbase = blockIdx.x * BPB + wid * SPW;
    const int ls0   = wid * SPW;

    // ---- stage layer-2 weights into smem ----
    #pragma unroll 4
    for (int i = tid; i < 2 * 8 * 128; i += WPB * 32) {
        const int m   = i >> 10;
        const int qq  = (i >> 7) & 7;
        const int row = i & 127;
        const float* src = (m ? w_hh2 : w_ih2) + row * HH + qq * 4;
        w2t[i] = *(const ulonglong2*)src;
    }
    __syncthreads();

    // ---- layer-1 weights -> registers ----
    u64 WR[64];    // WR[g*16 + 2qq + j]
    #pragma unroll
    for (int g = 0; g < 4; ++g) {
        const int row = g * HH + lane;
        #pragma unroll
        for (int qq = 0; qq < 8; ++qq) {
            ulonglong2 v = *(const ulonglong2*)(w_hh1 + row * HH + qq * 4);
            WR[g * 16 + 2 * qq]     = v.x;
            WR[g * 16 + 2 * qq + 1] = v.y;
        }
    }
    u64 wih[4][2];
    float bias1[4];
    #pragma unroll
    for (int g = 0; g < 4; ++g) {
        const int row = g * HH + lane;
        ulonglong2 vi = *(const ulonglong2*)(w_ih1 + row * NXX);
        wih[g][0] = vi.x;
        wih[g][1] = vi.y;
        bias1[g] = b_ih1[row] + b_hh1[row];
    }

    float* hb0 = hb + (ls0 + 0) * 64;
    float* hb1 = hb + (ls0 + 1) * 64;
    const float* x0 = x_main + (size_t)(bbase + 0) * (SS * NXX);
    const float* x1 = x_main + (size_t)(bbase + 1) * (SS * NXX);
    float* sy0 = sy + (ls0 + 0) * (SS * HH);
    float* sy1 = sy + (ls0 + 1) * (SS * HH);

    // ---- initial state from surface MLPs (both streams) ----
    float c0s, c1s;
    {
        float a10 = b_sfc1[lane], a20 = b_sfc2[lane];
        float a11 = a10, a21 = a20;
        #pragma unroll
        for (int k = 0; k < NSF; ++k) {
            const float w1v = w_sfc1[lane * NSF + k];
            const float w2v = w_sfc2[lane * NSF + k];
            const float s0 = x_sfc[(bbase + 0) * NSF + k];
            const float s1 = x_sfc[(bbase + 1) * NSF + k];
            a10 += s0 * w1v;  a11 += s1 * w1v;
            a20 += s0 * w2v;  a21 += s1 * w2v;
        }
        hb0[lane] = tanh_ap(a10);
        hb1[lane] = tanh_ap(a11);
        c0s = tanh_ap(a20);
        c1s = tanh_ap(a21);
    }
    __syncwarp();
    int buf = 0;

    // ================= layer 1: time-reversed scan, interleaved streams =================
    #pragma unroll 1
    for (int t = 0; t < SS; ++t) {
        const int s = SS - 1 - t;
        const ulonglong2 xv0 = *(const ulonglong2*)(x0 + s * NXX);
        const ulonglong2 xv1 = *(const ulonglong2*)(x1 + s * NXX);

        u64 A00 = pklo(bias1[0]), A01 = pklo(bias1[1]);
        u64 A02 = pklo(bias1[2]), A03 = pklo(bias1[3]);
        u64 A10 = pklo(bias1[0]), A11 = pklo(bias1[1]);
        u64 A12 = pklo(bias1[2]), A13 = pklo(bias1[3]);

        A00 = ffma2(xv0.x, wih[0][0], A00);  A10 = ffma2(xv1.x, wih[0][0], A10);
        A00 = ffma2(xv0.y, wih[0][1], A00);  A10 = ffma2(xv1.y, wih[0][1], A10);
        A01 = ffma2(xv0.x, wih[1][0], A01);  A11 = ffma2(xv1.x, wih[1][0], A11);
        A01 = ffma2(xv0.y, wih[1][1], A01);  A11 = ffma2(xv1.y, wih[1][1], A11);
        A02 = ffma2(xv0.x, wih[2][0], A02);  A12 = ffma2(xv1.x, wih[2][0], A12);
        A02 = ffma2(xv0.y, wih[2][1], A02);  A12 = ffma2(xv1.y, wih[2][1], A12);
        A03 = ffma2(xv0.x, wih[3][0], A03);  A13 = ffma2(xv1.x, wih[3][0], A13);
        A03 = ffma2(xv0.y, wih[3][1], A03);  A13 = ffma2(xv1.y, wih[3][1], A13);

        const ulonglong2* hp0 = (const ulonglong2*)(hb0 + buf * 32);
        const ulonglong2* hp1 = (const ulonglong2*)(hb1 + buf * 32);
        #pragma unroll
        for (int q = 0; q < 8; ++q) {
            const ulonglong2 hv0 = hp0[q];
            const ulonglong2 hv1 = hp1[q];
            A00 = ffma2(hv0.x, WR[2*q],      A00);  A10 = ffma2(hv1.x, WR[2*q],      A10);
            A00 = ffma2(hv0.y, WR[2*q+1],    A00);  A10 = ffma2(hv1.y, WR[2*q+1],    A10);
            A01 = ffma2(hv0.x, WR[16+2*q],   A01);  A11 = ffma2(hv1.x, WR[16+2*q],   A11);
            A01 = ffma2(hv0.y, WR[16+2*q+1], A01);  A11 = ffma2(hv1.y, WR[16+2*q+1], A11);
            A02 = ffma2(hv0.x, WR[32+2*q],   A02);  A12 = ffma2(hv1.x, WR[32+2*q],   A12);
            A02 = ffma2(hv0.y, WR[32+2*q+1], A02);  A12 = ffma2(hv1.y, WR[32+2*q+1], A12);
            A03 = ffma2(hv0.x, WR[48+2*q],   A03);  A13 = ffma2(hv1.x, WR[48+2*q],   A13);
            A03 = ffma2(hv0.y, WR[48+2*q+1], A03);  A13 = ffma2(hv1.y, WR[48+2*q+1], A13);
        }

        const float gi0 = hsum2(A00), gf0 = hsum2(A01), gg0 = hsum2(A02), go0 = hsum2(A03);
        const float gi1 = hsum2(A10), gf1 = hsum2(A11), gg1 = hsum2(A12), go1 = hsum2(A13);
        const float iv0 = sigm(gi0), fv0 = sigm(gf0), gv0 = tanh_ap(gg0), ov0 = sigm(go0);
        const float iv1 = sigm(gi1), fv1 = sigm(gf1), gv1 = tanh_ap(gg1), ov1 = sigm(go1);
        c0s = fv0 * c0s + iv0 * gv0;
        c1s = fv1 * c1s + iv1 * gv1;
        const float h0 = ov0 * tanh_ap(c0s);
        const float h1 = ov1 * tanh_ap(c1s);
        sy0[s * HH + lane] = h0;
        sy1[s * HH + lane] = h1;
        hb0[(buf ^ 1) * 32 + lane] = h0;
        hb1[(buf ^ 1) * 32 + lane] = h1;
        __syncwarp();
        buf ^= 1;
    }

    // ================= layer 2: forward scan =================
    float bias2[4];
    #pragma unroll
    for (int g = 0; g < 4; ++g)
        bias2[g] = b_ih2[g * HH + lane] + b_hh2[g * HH + lane];
    const float wo = w_out[lane];
    const float bo = b_out[0];

    c0s = 0.0f; c1s = 0.0f;
    hb0[buf * 32 + lane] = 0.0f;
    hb1[buf * 32 + lane] = 0.0f;
    __syncwarp();

    u64* sxg0 = sxg + ((ls0 + 0) * CH) * 2 * 32;   // [tt][pair][lane]
    u64* sxg1 = sxg + ((ls0 + 1) * CH) * 2 * 32;

    #pragma unroll 1
    for (int chk = 0; chk < SS / CH; ++chk) {
        const int t0 = chk * CH;

        // ---- phase A: input projection (w_ih2 in WR) ----
        #pragma unroll
        for (int g = 0; g < 4; ++g)
            #pragma unroll
            for (int qq = 0; qq < 8; ++qq) {
                ulonglong2 v = w2t[qq * 128 + g * 32 + lane];
                WR[g * 16 + 2 * qq]     = v.x;
                WR[g * 16 + 2 * qq + 1] = v.y;
            }
        #pragma unroll
        for (int tt = 0; tt < CH; ++tt) {
            const ulonglong2* yp0 = (const ulonglong2*)(sy0 + (t0 + tt) * HH);
            const ulonglong2* yp1 = (const ulonglong2*)(sy1 + (t0 + tt) * HH);
            u64 A00 = 0ull, A01 = 0ull, A02 = 0ull, A03 = 0ull;
            u64 A10 = 0ull, A11 = 0ull, A12 = 0ull, A13 = 0ull;
            #pragma unroll
            for (int q = 0; q < 8; ++q) {
                const ulonglong2 hv0 = yp0[q];
                const ulonglong2 hv1 = yp1[q];
                A00 = ffma2(hv0.x, WR[2*q],      A00);  A10 = ffma2(hv1.x, WR[2*q],      A10);
                A00 = ffma2(hv0.y, WR[2*q+1],    A00);  A10 = ffma2(hv1.y, WR[2*q+1],    A10);
                A01 = ffma2(hv0.x, WR[16+2*q],   A01);  A11 = ffma2(hv1.x, WR[16+2*q],   A11);
                A01 = ffma2(hv0.y, WR[16+2*q+1], A01);  A11 = ffma2(hv1.y, WR[16+2*q+1], A11);
                A02 = ffma2(hv0.x, WR[32+2*q],   A02);  A12 = ffma2(hv1.x, WR[32+2*q],   A12);
                A02 = ffma2(hv0.y, WR[32+2*q+1], A02);  A12 = ffma2(hv1.y, WR[32+2*q+1], A12);
                A03 = ffma2(hv0.x, WR[48+2*q],   A03);  A13 = ffma2(hv1.x, WR[48+2*q],   A13);
                A03 = ffma2(hv0.y, WR[48+2*q+1], A03);  A13 = ffma2(hv1.y, WR[48+2*q+1], A13);
            }
            // lane-private scratch: no syncwarp needed (same-lane RAW)
            sxg0[(tt * 2 + 0) * 32 + lane] = pk2(hsum2(A00) + bias2[0], hsum2(A01) + bias2[1]);
            sxg0[(tt * 2 + 1) * 32 + lane] = pk2(hsum2(A02) + bias2[2], hsum2(A03) + bias2[3]);
            sxg1[(tt * 2 + 0) * 32 + lane] = pk2(hsum2(A10) + bias2[0], hsum2(A11) + bias2[1]);
            sxg1[(tt * 2 + 1) * 32 + lane] = pk2(hsum2(A12) + bias2[2], hsum2(A13) + bias2[3]);
        }

        // ---- phase B: recurrence (w_hh2 in WR) ----
        #pragma unroll
        for (int g = 0; g < 4; ++g)
            #pragma unroll
            for (int qq = 0; qq < 8; ++qq) {
                ulonglong2 v = w2t[1024 + qq * 128 + g * 32 + lane];
                WR[g * 16 + 2 * qq]     = v.x;
                WR[g * 16 + 2 * qq + 1] = v.y;
            }
        #pragma unroll
        for (int tt = 0; tt < CH; ++tt) {
            float x00, x01, x02, x03, x10, x11, x12, x13;
            up2(sxg0[(tt * 2 + 0) * 32 + lane], x00, x01);
            up2(sxg0[(tt * 2 + 1) * 32 + lane], x02, x03);
            up2(sxg1[(tt * 2 + 0) * 32 + lane], x10, x11);
            up2(sxg1[(tt * 2 + 1) * 32 + lane], x12, x13);
            u64 A00 = pklo(x00), A01 = pklo(x01), A02 = pklo(x02), A03 = pklo(x03);
            u64 A10 = pklo(x10), A11 = pklo(x11), A12 = pklo(x12), A13 = pklo(x13);

            const ulonglong2* hp0 = (const ulonglong2*)(hb0 + buf * 32);
            const ulonglong2* hp1 = (const ulonglong2*)(hb1 + buf * 32);
            #pragma unroll
            for (int q = 0; q < 8; ++q) {
                const ulonglong2 hv0 = hp0[q];
                const ulonglong2 hv1 = hp1[q];
                A00 = ffma2(hv0.x, WR[2*q],      A00);  A10 = ffma2(hv1.x, WR[2*q],      A10);
                A00 = ffma2(hv0.y, WR[2*q+1],    A00);  A10 = ffma2(hv1.y, WR[2*q+1],    A10);
                A01 = ffma2(hv0.x, WR[16+2*q],   A01);  A11 = ffma2(hv1.x, WR[16+2*q],   A11);
                A01 = ffma2(hv0.y, WR[16+2*q+1], A01);  A11 = ffma2(hv1.y, WR[16+2*q+1], A11);
                A02 = ffma2(hv0.x, WR[32+2*q],   A02);  A12 = ffma2(hv1.x, WR[32+2*q],   A12);
                A02 = ffma2(hv0.y, WR[32+2*q+1], A02);  A12 = ffma2(hv1.y, WR[32+2*q+1], A12);
                A03 = ffma2(hv0.x, WR[48+2*q],   A03);  A13 = ffma2(hv1.x, WR[48+2*q],   A13);
                A03 = ffma2(hv0.y, WR[48+2*q+1], A03);  A13 = ffma2(hv1.y, WR[48+2*q+1], A13);
            }
            const float gi0 = hsum2(A00), gf0 = hsum2(A01), gg0 = hsum2(A02), go0 = hsum2(A03);
            const float gi1 = hsum2(A10), gf1 = hsum2(A11), gg1 = hsum2(A12), go1 = hsum2(A13);
            const float iv0 = sigm(gi0), fv0 = sigm(gf0), gv0 = tanh_ap(gg0), ov0 = sigm(go0);
            const float iv1 = sigm(gi1), fv1 = sigm(gf1), gv1 = tanh_ap(gg1), ov1 = sigm(go1);
            c0s = fv0 * c0s + iv0 * gv0;
            c1s = fv1 * c1s + iv1 * gv1;
            const float h20 = ov0 * tanh_ap(c0s);
            const float h21 = ov1 * tanh_ap(c1s);
            hb0[(buf ^ 1) * 32 + lane] = h20;
            hb1[(buf ^ 1) * 32 + lane] = h21;
            __syncwarp();
            buf ^= 1;

            // output head for both streams (packed reduction)
            u64 po = pk2(h20 * wo, h21 * wo);
            #pragma unroll
            for (int off = 16; off; off >>= 1) {
                float plo, phi;
                up2(po, plo, phi);
                plo += __shfl_xor_sync(FULLMASK, plo, off);
                phi += __shfl_xor_sync(FULLMASK, phi, off);
                po = pk2(plo, phi);
            }
            if (lane == 0) {
                float plo, phi;
                up2(po, plo, phi);
                out[(size_t)(bbase + 0) * SS + t0 + tt] = plo + bo;
                out[(size_t)(bbase + 1) * SS + t0 + tt] = phi + bo;
            }
        }
    }
}

extern "C" void kernel_launch(void* const* d_in, const int* in_sizes, int n_in,
                              void* d_out, int out_size)
{
    const float* x_main = (const float*)d_in[0];
    const float* x_sfc  = (const float*)d_in[1];
    const float* w_sfc1 = (const float*)d_in[2];
    const float* b_sfc1 = (const float*)d_in[3];
    const float* w_sfc2 = (const float*)d_in[4];
    const float* b_sfc2 = (const float*)d_in[5];
    const float* w_ih1  = (const float*)d_in[6];
    const float* w_hh1  = (const float*)d_in[7];
    const float* b_ih1  = (const float*)d_in[8];
    const float* b_hh1  = (const float*)d_in[9];
    const float* w_ih2  = (const float*)d_in[10];
    const float* w_hh2  = (const float*)d_in[11];
    const float* b_ih2  = (const float*)d_in[12];
    const float* b_hh2  = (const float*)d_in[13];
    const float* w_out  = (const float*)d_in[14];
    const float* b_out  = (const float*)d_in[15];
    float* out = (float*)d_out;

    static bool attr_set = false;
    if (!attr_set) {
        cudaFuncSetAttribute(lstm_fused6, cudaFuncAttributeMaxDynamicSharedMemorySize, SMEM_BYTES);
        attr_set = true;
    }

    const int blocks = NB / BPB;   // 1024
    lstm_fused6<<<blocks, WPB * 32, SMEM_BYTES>>>(
        x_main, x_sfc, w_sfc1, b_sfc1, w_sfc2, b_sfc2,
        w_ih1, w_hh1, b_ih1, b_hh1,
        w_ih2, w_hh2, b_ih2, b_hh2,
        w_out, b_out, out);
}

// round 7
// speedup vs baseline: 1.2192x; 1.2192x over previous
#include <cuda_runtime.h>
#include <cstdint>

typedef unsigned long long u64;

#define NB   8192
#define SS   64
#define NXX  4
#define NSF  5
#define HH   32
#define WPB  4          // warps per block
#define SPW  2          // batch streams per warp
#define BPB  (WPB*SPW)  // 8 batch elements per block
#define CH   4          // layer-2 time chunk
#define FULLMASK 0xffffffffu

// ---------- packed f32x2 helpers ----------
static __device__ __forceinline__ u64 ffma2(u64 a, u64 b, u64 c) {
    u64 d; asm("fma.rn.f32x2 %0, %1, %2, %3;" : "=l"(d) : "l"(a), "l"(b), "l"(c)); return d;
}
static __device__ __forceinline__ u64 pk2(float lo, float hi) {
    u64 r; asm("mov.b64 %0, {%1, %2};" : "=l"(r) : "f"(lo), "f"(hi)); return r;
}
static __device__ __forceinline__ u64 pklo(float lo) {
    u64 r; asm("mov.b64 %0, {%1, %2};" : "=l"(r) : "f"(lo), "f"(0.0f)); return r;
}
static __device__ __forceinline__ void up2(u64 v, float& lo, float& hi) {
    asm("mov.b64 {%0, %1}, %2;" : "=f"(lo), "=f"(hi) : "l"(v));
}
static __device__ __forceinline__ float hsum2(u64 v) {
    float x, y; up2(v, x, y); return x + y;
}

// ---------- fast activations (MUFU.TANH) ----------
static __device__ __forceinline__ float tanh_ap(float x) {
    float r; asm("tanh.approx.f32 %0, %1;" : "=f"(r) : "f"(x)); return r;
}
static __device__ __forceinline__ float sigm(float x) {
    return fmaf(tanh_ap(0.5f * x), 0.5f, 0.5f);
}

// ---- shared memory (bytes) ----
// w2t : ulonglong2[2][8][128]  layer-2 weights                       32768
// sy  : float[8][64*32]        layer-1 outputs                       65536
// hb  : float[8][2][32]        h broadcast double buffers             2048
#define OFF_W2T  0
#define OFF_SY   32768
#define OFF_HB   (32768 + 65536)
#define SMEM_BYTES (OFF_HB + 2048)

__global__ void __launch_bounds__(WPB * 32, 2)
lstm_fused7(const float* __restrict__ x_main,
            const float* __restrict__ x_sfc,
            const float* __restrict__ w_sfc1, const float* __restrict__ b_sfc1,
            const float* __restrict__ w_sfc2, const float* __restrict__ b_sfc2,
            const float* __restrict__ w_ih1,  const float* __restrict__ w_hh1,
            const float* __restrict__ b_ih1,  const float* __restrict__ b_hh1,
            const float* __restrict__ w_ih2,  const float* __restrict__ w_hh2,
            const float* __restrict__ b_ih2,  const float* __restrict__ b_hh2,
            const float* __restrict__ w_out,  const float* __restrict__ b_out,
            float* __restrict__ out)
{
    extern __shared__ char smem[];
    ulonglong2* w2t = (ulonglong2*)(smem + OFF_W2T);   // [(m*8+qq)*128 + row]
    float* sy  = (float*)(smem + OFF_SY);
    float* hb  = (float*)(smem + OFF_HB);

    const int tid  = threadIdx.x;
    const int wid  = tid >> 5;
    const int lane = tid & 31;
    const int bbase = blockIdx.x * BPB + wid * SPW;
    const int ls0   = wid * SPW;

    // ---- stage layer-2 weights into smem ----
    #pragma unroll 4
    for (int i = tid; i < 2 * 8 * 128; i += WPB * 32) {
        const int m   = i >> 10;
        const int qq  = (i >> 7) & 7;
        const int row = i & 127;
        const float* src = (m ? w_hh2 : w_ih2) + row * HH + qq * 4;
        w2t[i] = *(const ulonglong2*)src;
    }
    __syncthreads();

    // ---- layer-1 weights -> registers ----
    u64 WR[64];    // WR[g*16 + 2qq + j]
    #pragma unroll
    for (int g = 0; g < 4; ++g) {
        const int row = g * HH + lane;
        #pragma unroll
        for (int qq = 0; qq < 8; ++qq) {
            ulonglong2 v = *(const ulonglong2*)(w_hh1 + row * HH + qq * 4);
            WR[g * 16 + 2 * qq]     = v.x;
            WR[g * 16 + 2 * qq + 1] = v.y;
        }
    }
    u64 wih[4][2];
    float bias1[4];
    #pragma unroll
    for (int g = 0; g < 4; ++g) {
        const int row = g * HH + lane;
        ulonglong2 vi = *(const ulonglong2*)(w_ih1 + row * NXX);
        wih[g][0] = vi.x;
        wih[g][1] = vi.y;
        bias1[g] = b_ih1[row] + b_hh1[row];
    }

    float* hb0 = hb + (ls0 + 0) * 64;
    float* hb1 = hb + (ls0 + 1) * 64;
    const float* x0 = x_main + (size_t)(bbase + 0) * (SS * NXX);
    const float* x1 = x_main + (size_t)(bbase + 1) * (SS * NXX);
    float* sy0 = sy + (ls0 + 0) * (SS * HH);
    float* sy1 = sy + (ls0 + 1) * (SS * HH);

    // ---- initial state from surface MLPs (both streams) ----
    float c0s, c1s;
    {
        float a10 = b_sfc1[lane], a20 = b_sfc2[lane];
        float a11 = a10, a21 = a20;
        #pragma unroll
        for (int k = 0; k < NSF; ++k) {
            const float w1v = w_sfc1[lane * NSF + k];
            const float w2v = w_sfc2[lane * NSF + k];
            const float s0 = x_sfc[(bbase + 0) * NSF + k];
            const float s1 = x_sfc[(bbase + 1) * NSF + k];
            a10 += s0 * w1v;  a11 += s1 * w1v;
            a20 += s0 * w2v;  a21 += s1 * w2v;
        }
        hb0[lane] = tanh_ap(a10);
        hb1[lane] = tanh_ap(a11);
        c0s = tanh_ap(a20);
        c1s = tanh_ap(a21);
    }
    __syncwarp();
    int buf = 0;

    // ================= layer 1: time-reversed scan, interleaved streams =================
    #pragma unroll 1
    for (int t = 0; t < SS; ++t) {
        const int s = SS - 1 - t;
        const ulonglong2 xv0 = *(const ulonglong2*)(x0 + s * NXX);
        const ulonglong2 xv1 = *(const ulonglong2*)(x1 + s * NXX);

        u64 A00 = pklo(bias1[0]), A01 = pklo(bias1[1]);
        u64 A02 = pklo(bias1[2]), A03 = pklo(bias1[3]);
        u64 A10 = pklo(bias1[0]), A11 = pklo(bias1[1]);
        u64 A12 = pklo(bias1[2]), A13 = pklo(bias1[3]);

        A00 = ffma2(xv0.x, wih[0][0], A00);  A10 = ffma2(xv1.x, wih[0][0], A10);
        A00 = ffma2(xv0.y, wih[0][1], A00);  A10 = ffma2(xv1.y, wih[0][1], A10);
        A01 = ffma2(xv0.x, wih[1][0], A01);  A11 = ffma2(xv1.x, wih[1][0], A11);
        A01 = ffma2(xv0.y, wih[1][1], A01);  A11 = ffma2(xv1.y, wih[1][1], A11);
        A02 = ffma2(xv0.x, wih[2][0], A02);  A12 = ffma2(xv1.x, wih[2][0], A12);
        A02 = ffma2(xv0.y, wih[2][1], A02);  A12 = ffma2(xv1.y, wih[2][1], A12);
        A03 = ffma2(xv0.x, wih[3][0], A03);  A13 = ffma2(xv1.x, wih[3][0], A13);
        A03 = ffma2(xv0.y, wih[3][1], A03);  A13 = ffma2(xv1.y, wih[3][1], A13);

        const ulonglong2* hp0 = (const ulonglong2*)(hb0 + buf * 32);
        const ulonglong2* hp1 = (const ulonglong2*)(hb1 + buf * 32);
        #pragma unroll
        for (int q = 0; q < 8; ++q) {
            const ulonglong2 hv0 = hp0[q];
            const ulonglong2 hv1 = hp1[q];
            A00 = ffma2(hv0.x, WR[2*q],      A00);  A10 = ffma2(hv1.x, WR[2*q],      A10);
            A00 = ffma2(hv0.y, WR[2*q+1],    A00);  A10 = ffma2(hv1.y, WR[2*q+1],    A10);
            A01 = ffma2(hv0.x, WR[16+2*q],   A01);  A11 = ffma2(hv1.x, WR[16+2*q],   A11);
            A01 = ffma2(hv0.y, WR[16+2*q+1], A01);  A11 = ffma2(hv1.y, WR[16+2*q+1], A11);
            A02 = ffma2(hv0.x, WR[32+2*q],   A02);  A12 = ffma2(hv1.x, WR[32+2*q],   A12);
            A02 = ffma2(hv0.y, WR[32+2*q+1], A02);  A12 = ffma2(hv1.y, WR[32+2*q+1], A12);
            A03 = ffma2(hv0.x, WR[48+2*q],   A03);  A13 = ffma2(hv1.x, WR[48+2*q],   A13);
            A03 = ffma2(hv0.y, WR[48+2*q+1], A03);  A13 = ffma2(hv1.y, WR[48+2*q+1], A13);
        }

        const float gi0 = hsum2(A00), gf0 = hsum2(A01), gg0 = hsum2(A02), go0 = hsum2(A03);
        const float gi1 = hsum2(A10), gf1 = hsum2(A11), gg1 = hsum2(A12), go1 = hsum2(A13);
        const float iv0 = sigm(gi0), fv0 = sigm(gf0), gv0 = tanh_ap(gg0), ov0 = sigm(go0);
        const float iv1 = sigm(gi1), fv1 = sigm(gf1), gv1 = tanh_ap(gg1), ov1 = sigm(go1);
        c0s = fv0 * c0s + iv0 * gv0;
        c1s = fv1 * c1s + iv1 * gv1;
        const float h0 = ov0 * tanh_ap(c0s);
        const float h1 = ov1 * tanh_ap(c1s);
        sy0[s * HH + lane] = h0;
        sy1[s * HH + lane] = h1;
        hb0[(buf ^ 1) * 32 + lane] = h0;
        hb1[(buf ^ 1) * 32 + lane] = h1;
        __syncwarp();
        buf ^= 1;
    }

    // ================= layer 2: forward scan =================
    float bias2[4];
    #pragma unroll
    for (int g = 0; g < 4; ++g)
        bias2[g] = b_ih2[g * HH + lane] + b_hh2[g * HH + lane];
    const float wo = w_out[lane];
    const float bo = b_out[0];

    c0s = 0.0f; c1s = 0.0f;
    hb0[buf * 32 + lane] = 0.0f;
    hb1[buf * 32 + lane] = 0.0f;
    __syncwarp();

    u64 xg0[CH][2];   // stream 0: per tt, gates (0,1) and (2,3)
    u64 xg1[CH][2];   // stream 1

    #pragma unroll 1
    for (int chk = 0; chk < SS / CH; ++chk) {
        const int t0 = chk * CH;

        // ---- phase A: input projection (w_ih2 in WR) ----
        #pragma unroll
        for (int g = 0; g < 4; ++g)
            #pragma unroll
            for (int qq = 0; qq < 8; ++qq) {
                ulonglong2 v = w2t[qq * 128 + g * 32 + lane];
                WR[g * 16 + 2 * qq]     = v.x;
                WR[g * 16 + 2 * qq + 1] = v.y;
            }
        #pragma unroll
        for (int tt = 0; tt < CH; ++tt) {
            const ulonglong2* yp0 = (const ulonglong2*)(sy0 + (t0 + tt) * HH);
            const ulonglong2* yp1 = (const ulonglong2*)(sy1 + (t0 + tt) * HH);
            u64 A00 = 0ull, A01 = 0ull, A02 = 0ull, A03 = 0ull;
            u64 A10 = 0ull, A11 = 0ull, A12 = 0ull, A13 = 0ull;
            #pragma unroll
            for (int q = 0; q < 8; ++q) {
                const ulonglong2 hv0 = yp0[q];
                const ulonglong2 hv1 = yp1[q];
                A00 = ffma2(hv0.x, WR[2*q],      A00);  A10 = ffma2(hv1.x, WR[2*q],      A10);
                A00 = ffma2(hv0.y, WR[2*q+1],    A00);  A10 = ffma2(hv1.y, WR[2*q+1],    A10);
                A01 = ffma2(hv0.x, WR[16+2*q],   A01);  A11 = ffma2(hv1.x, WR[16+2*q],   A11);
                A01 = ffma2(hv0.y, WR[16+2*q+1], A01);  A11 = ffma2(hv1.y, WR[16+2*q+1], A11);
                A02 = ffma2(hv0.x, WR[32+2*q],   A02);  A12 = ffma2(hv1.x, WR[32+2*q],   A12);
                A02 = ffma2(hv0.y, WR[32+2*q+1], A02);  A12 = ffma2(hv1.y, WR[32+2*q+1], A12);
                A03 = ffma2(hv0.x, WR[48+2*q],   A03);  A13 = ffma2(hv1.x, WR[48+2*q],   A13);
                A03 = ffma2(hv0.y, WR[48+2*q+1], A03);  A13 = ffma2(hv1.y, WR[48+2*q+1], A13);
            }
            xg0[tt][0] = pk2(hsum2(A00) + bias2[0], hsum2(A01) + bias2[1]);
            xg0[tt][1] = pk2(hsum2(A02) + bias2[2], hsum2(A03) + bias2[3]);
            xg1[tt][0] = pk2(hsum2(A10) + bias2[0], hsum2(A11) + bias2[1]);
            xg1[tt][1] = pk2(hsum2(A12) + bias2[2], hsum2(A13) + bias2[3]);
        }

        // ---- phase B: recurrence (w_hh2 in WR) ----
        #pragma unroll
        for (int g = 0; g < 4; ++g)
            #pragma unroll
            for (int qq = 0; qq < 8; ++qq) {
                ulonglong2 v = w2t[1024 + qq * 128 + g * 32 + lane];
                WR[g * 16 + 2 * qq]     = v.x;
                WR[g * 16 + 2 * qq + 1] = v.y;
            }
        #pragma unroll
        for (int tt = 0; tt < CH; ++tt) {
            float x00, x01, x02, x03, x10, x11, x12, x13;
            up2(xg0[tt][0], x00, x01);
            up2(xg0[tt][1], x02, x03);
            up2(xg1[tt][0], x10, x11);
            up2(xg1[tt][1], x12, x13);
            u64 A00 = pklo(x00), A01 = pklo(x01), A02 = pklo(x02), A03 = pklo(x03);
            u64 A10 = pklo(x10), A11 = pklo(x11), A12 = pklo(x12), A13 = pklo(x13);

            const ulonglong2* hp0 = (const ulonglong2*)(hb0 + buf * 32);
            const ulonglong2* hp1 = (const ulonglong2*)(hb1 + buf * 32);
            #pragma unroll
            for (int q = 0; q < 8; ++q) {
                const ulonglong2 hv0 = hp0[q];
                const ulonglong2 hv1 = hp1[q];
                A00 = ffma2(hv0.x, WR[2*q],      A00);  A10 = ffma2(hv1.x, WR[2*q],      A10);
                A00 = ffma2(hv0.y, WR[2*q+1],    A00);  A10 = ffma2(hv1.y, WR[2*q+1],    A10);
                A01 = ffma2(hv0.x, WR[16+2*q],   A01);  A11 = ffma2(hv1.x, WR[16+2*q],   A11);
                A01 = ffma2(hv0.y, WR[16+2*q+1], A01);  A11 = ffma2(hv1.y, WR[16+2*q+1], A11);
                A02 = ffma2(hv0.x, WR[32+2*q],   A02);  A12 = ffma2(hv1.x, WR[32+2*q],   A12);
                A02 = ffma2(hv0.y, WR[32+2*q+1], A02);  A12 = ffma2(hv1.y, WR[32+2*q+1], A12);
                A03 = ffma2(hv0.x, WR[48+2*q],   A03);  A13 = ffma2(hv1.x, WR[48+2*q],   A13);
                A03 = ffma2(hv0.y, WR[48+2*q+1], A03);  A13 = ffma2(hv1.y, WR[48+2*q+1], A13);
            }
            const float gi0 = hsum2(A00), gf0 = hsum2(A01), gg0 = hsum2(A02), go0 = hsum2(A03);
            const float gi1 = hsum2(A10), gf1 = hsum2(A11), gg1 = hsum2(A12), go1 = hsum2(A13);
            const float iv0 = sigm(gi0), fv0 = sigm(gf0), gv0 = tanh_ap(gg0), ov0 = sigm(go0);
            const float iv1 = sigm(gi1), fv1 = sigm(gf1), gv1 = tanh_ap(gg1), ov1 = sigm(go1);
            c0s = fv0 * c0s + iv0 * gv0;
            c1s = fv1 * c1s + iv1 * gv1;
            const float h20 = ov0 * tanh_ap(c0s);
            const float h21 = ov1 * tanh_ap(c1s);
            hb0[(buf ^ 1) * 32 + lane] = h20;
            hb1[(buf ^ 1) * 32 + lane] = h21;
            __syncwarp();
            buf ^= 1;

            // output head for both streams (packed reduction)
            float plo = h20 * wo, phi = h21 * wo;
            #pragma unroll
            for (int off = 16; off; off >>= 1) {
                plo += __shfl_xor_sync(FULLMASK, plo, off);
                phi += __shfl_xor_sync(FULLMASK, phi, off);
            }
            if (lane == 0) {
                out[(size_t)(bbase + 0) * SS + t0 + tt] = plo + bo;
                out[(size_t)(bbase + 1) * SS + t0 + tt] = phi + bo;
            }
        }
    }
}

extern "C" void kernel_launch(void* const* d_in, const int* in_sizes, int n_in,
                              void* d_out, int out_size)
{
    const float* x_main = (const float*)d_in[0];
    const float* x_sfc  = (const float*)d_in[1];
    const float* w_sfc1 = (const float*)d_in[2];
    const float* b_sfc1 = (const float*)d_in[3];
    const float* w_sfc2 = (const float*)d_in[4];
    const float* b_sfc2 = (const float*)d_in[5];
    const float* w_ih1  = (const float*)d_in[6];
    const float* w_hh1  = (const float*)d_in[7];
    const float* b_ih1  = (const float*)d_in[8];
    const float* b_hh1  = (const float*)d_in[9];
    const float* w_ih2  = (const float*)d_in[10];
    const float* w_hh2  = (const float*)d_in[11];
    const float* b_ih2  = (const float*)d_in[12];
    const float* b_hh2  = (const float*)d_in[13];
    const float* w_out  = (const float*)d_in[14];
    const float* b_out  = (const float*)d_in[15];
    float* out = (float*)d_out;

    static bool attr_set = false;
    if (!attr_set) {
        cudaFuncSetAttribute(lstm_fused7, cudaFuncAttributeMaxDynamicSharedMemorySize, SMEM_BYTES);
        attr_set = true;
    }

    const int blocks = NB / BPB;   // 1024
    lstm_fused7<<<blocks, WPB * 32, SMEM_BYTES>>>(
        x_main, x_sfc, w_sfc1, b_sfc1, w_sfc2, b_sfc2,
        w_ih1, w_hh1, b_ih1, b_hh1,
        w_ih2, w_hh2, b_ih2, b_hh2,
        w_out, b_out, out);
}